// round 15
// baseline (speedup 1.0000x reference)
#include <cuda_runtime.h>
#include <cuda_fp16.h>
#include <cstdint>
#include <math.h>

#define BATCH 4
#define SEQ   2048
#define DIM   1024
#define HEADS 16
#define HD    64
#define MTOT  (BATCH*SEQ)   // 8192

// Scratch (allocation-free rule: __device__ globals)
__device__ __half g_w  [4][DIM*DIM];      // fp16 copies of Wq,Wk,Wv,Wo
__device__ __half g_qh [MTOT*DIM];        // projected q (pre-scaled 0.125)
__device__ __half g_kh [MTOT*DIM];
__device__ __half g_vh [MTOT*DIM];
__device__ __half g_ohh[MTOT*DIM];        // attention output heads
__device__ float  g_rl [BATCH*HEADS*SEQ];
// exp(scores), FRAGMENT-BLOCKED: tile (bh,tile_t,tile_s) of 16x64 halves
// = 512 words; word addr = tile*512 + word_idx*32 + lane.
__device__ unsigned g_expa[(size_t)BATCH*HEADS*(SEQ/16)*(SEQ/64)*512];

// ---------------------------------------------------------------------------
// helpers
// ---------------------------------------------------------------------------
__device__ __forceinline__ void mma16(float c[4],
    unsigned a0, unsigned a1, unsigned a2, unsigned a3,
    unsigned b0, unsigned b1)
{
    asm volatile(
      "mma.sync.aligned.m16n8k16.row.col.f32.f16.f16.f32 "
      "{%0,%1,%2,%3},{%4,%5,%6,%7},{%8,%9},{%0,%1,%2,%3};"
      : "+f"(c[0]), "+f"(c[1]), "+f"(c[2]), "+f"(c[3])
      : "r"(a0), "r"(a1), "r"(a2), "r"(a3), "r"(b0), "r"(b1));
}
__device__ __forceinline__ void ldmx4(unsigned r[4], unsigned addr)
{
    asm volatile(
      "ldmatrix.sync.aligned.m8n8.x4.shared.b16 {%0,%1,%2,%3}, [%4];"
      : "=r"(r[0]), "=r"(r[1]), "=r"(r[2]), "=r"(r[3]) : "r"(addr));
}
__device__ __forceinline__ void ldmx4t(unsigned r[4], unsigned addr)
{
    asm volatile(
      "ldmatrix.sync.aligned.m8n8.x4.trans.shared.b16 {%0,%1,%2,%3}, [%4];"
      : "=r"(r[0]), "=r"(r[1]), "=r"(r[2]), "=r"(r[3]) : "r"(addr));
}
__device__ __forceinline__ unsigned h2u(__half2 h) { return *(unsigned*)&h; }
__device__ __forceinline__ void cpa16(unsigned dst, const void* src) {
    asm volatile("cp.async.cg.shared.global [%0], [%1], 16;\n" :: "r"(dst), "l"(src));
}
__device__ __forceinline__ uint32_t smem_u32(const void* p) {
    uint32_t a;
    asm("{ .reg .u64 t; cvta.to.shared.u64 t, %1; cvt.u32.u64 %0, t; }"
        : "=r"(a) : "l"(p));
    return a;
}

// ---------------------------------------------------------------------------
// fp32 -> fp16 convert for the 4 weight matrices only (grid.y selects)
// ---------------------------------------------------------------------------
__global__ void __launch_bounds__(256) cvt_w(
    const float* wq, const float* wk, const float* wv, const float* wo)
{
    const int y = blockIdx.y;
    const float* src = (y == 0) ? wq : (y == 1) ? wk : (y == 2) ? wv : wo;
    __half* dst = g_w[y];
    const int n4 = DIM*DIM/4;
    for (int i = blockIdx.x*256 + threadIdx.x; i < n4; i += gridDim.x*256) {
        float4 f = *(const float4*)(src + (size_t)i*4);
        *(__half2*)(dst + (size_t)i*4)     = __floats2half2_rn(f.x, f.y);
        *(__half2*)(dst + (size_t)i*4 + 2) = __floats2half2_rn(f.z, f.w);
    }
}

// ---------------------------------------------------------------------------
// fp16 NT GEMM body, 4-stage pipeline, one barrier per k-tile.
// AF32: A operand is fp32 in gmem, converted inline (LDG.128 -> cvt -> STS);
//       otherwise A uses fp16 cp.async. W always fp16 cp.async.
// Block tile 128x128, BK=32, 256 threads, warp tile 64x32.
// omode: 0 fp32-out, 1 fp16-out, 2 fp16-out scaled 0.125.
// ---------------------------------------------------------------------------
#define LDH   40
#define G_STB (128*LDH)                 // halves per stage-operand (10240 B)
#define G_SMEM_BYTES (4 * 2 * G_STB * 2)  // 81920

template<bool AF32>
__device__ __forceinline__ void gemm_body(
    const void* __restrict__ Av, const __half* __restrict__ W,
    const float* __restrict__ bias, void* __restrict__ Cv,
    __half* smp, unsigned sb, int m0, int n0, int omode)
{
    const int tid  = threadIdx.x;
    const int lane = tid & 31, warp = tid >> 5;
    const int g = lane >> 2, t = lane & 3;
    const int wm = (warp >> 2) << 6, wn = (warp & 3) << 5;
    const __half* Abh = (const __half*)Av + (size_t)m0 * DIM;
    const float*  Abf = (const float*) Av + (size_t)m0 * DIM;
    const __half* Wb  = W + (size_t)n0 * DIM;

    // per-thread chunk coords: 512 16B-chunks (fp16) per operand per stage
    const int ch0 = tid << 1, ch1 = ch0 + 1;
    const int r0 = ch0 >> 2, c0 = (ch0 & 3) << 3;
    const int r1 = ch1 >> 2, c1 = (ch1 & 3) << 3;
    const unsigned aOff0 = (unsigned)((r0*LDH + c0) << 1);
    const unsigned aOff1 = (unsigned)((r1*LDH + c1) << 1);

    const int aRow = wm + (lane & 15);
    const int aKof = (lane >> 4) << 3;
    const int bRow = wn + ((lane >> 4) << 3) + (lane & 7);
    const int bKof = ((lane >> 3) & 1) << 3;

    float acc[4][4][4];
    #pragma unroll
    for (int i = 0; i < 4; i++)
        #pragma unroll
        for (int j = 0; j < 4; j++)
            #pragma unroll
            for (int v = 0; v < 4; v++) acc[i][j][v] = 0.f;

    // ---- A-stage fill (either inline-cvt STS or cp.async) ----
    #define FILL_A(stB, k0)                                                   \
        if (AF32) {                                                           \
            float4 fa = *(const float4*)(Abf + (size_t)r0*DIM + (k0) + c0);   \
            float4 fb = *(const float4*)(Abf + (size_t)r0*DIM + (k0) + c0 + 4);\
            float4 fc = *(const float4*)(Abf + (size_t)r1*DIM + (k0) + c1);   \
            float4 fd = *(const float4*)(Abf + (size_t)r1*DIM + (k0) + c1 + 4);\
            uint4 u0, u1;                                                     \
            u0.x = h2u(__floats2half2_rn(fa.x, fa.y));                        \
            u0.y = h2u(__floats2half2_rn(fa.z, fa.w));                        \
            u0.z = h2u(__floats2half2_rn(fb.x, fb.y));                        \
            u0.w = h2u(__floats2half2_rn(fb.z, fb.w));                        \
            u1.x = h2u(__floats2half2_rn(fc.x, fc.y));                        \
            u1.y = h2u(__floats2half2_rn(fc.z, fc.w));                        \
            u1.z = h2u(__floats2half2_rn(fd.x, fd.y));                        \
            u1.w = h2u(__floats2half2_rn(fd.z, fd.w));                        \
            *(uint4*)((char*)smp + (stB) + aOff0) = u0;                       \
            *(uint4*)((char*)smp + (stB) + aOff1) = u1;                       \
        } else {                                                              \
            cpa16(sb + (stB) + aOff0, Abh + (size_t)r0*DIM + (k0) + c0);      \
            cpa16(sb + (stB) + aOff1, Abh + (size_t)r1*DIM + (k0) + c1);      \
        }

    // prologue: k-tiles 0..2 -> stages 0..2
    #pragma unroll
    for (int s = 0; s < 3; s++) {
        const unsigned stB = (unsigned)(s * 2 * G_STB) << 1;
        const int k0 = s << 5;
        FILL_A(stB, k0)
        cpa16(sb + stB + (G_STB << 1) + aOff0, Wb + (size_t)r0 * DIM + k0 + c0);
        cpa16(sb + stB + (G_STB << 1) + aOff1, Wb + (size_t)r1 * DIM + k0 + c1);
        asm volatile("cp.async.commit_group;\n");
    }

    for (int kt = 0; kt < 32; kt++) {
        if (kt <= 29)      asm volatile("cp.async.wait_group 2;\n");
        else if (kt == 30) asm volatile("cp.async.wait_group 1;\n");
        else               asm volatile("cp.async.wait_group 0;\n");
        __syncthreads();

        // loads for kt+3 target buffer (kt+3)&3 == (kt-1)&3, finished pre-barrier
        if (kt + 3 < 32) {
            const int s = (kt + 3) & 3;
            const unsigned stB = (unsigned)(s * 2 * G_STB) << 1;
            const int k0 = (kt + 3) << 5;
            FILL_A(stB, k0)
            cpa16(sb + stB + (G_STB << 1) + aOff0, Wb + (size_t)r0 * DIM + k0 + c0);
            cpa16(sb + stB + (G_STB << 1) + aOff1, Wb + (size_t)r1 * DIM + k0 + c1);
            asm volatile("cp.async.commit_group;\n");
        }

        const unsigned aB = sb + ((unsigned)((kt & 3) * 2 * G_STB) << 1);
        const unsigned wB = aB + (G_STB << 1);
        #pragma unroll
        for (int s = 0; s < 2; s++) {
            const int kh = s << 4;
            unsigned af[4][4], bf[4][2];
            #pragma unroll
            for (int mt = 0; mt < 4; mt++)
                ldmx4(af[mt], aB +
                      (unsigned)(((aRow + (mt << 4))*LDH + kh + aKof) << 1));
            #pragma unroll
            for (int p = 0; p < 2; p++) {
                unsigned bx[4];
                ldmx4(bx, wB +
                      (unsigned)(((bRow + (p << 4))*LDH + kh + bKof) << 1));
                bf[2*p][0]   = bx[0]; bf[2*p][1]   = bx[1];
                bf[2*p+1][0] = bx[2]; bf[2*p+1][1] = bx[3];
            }
            #pragma unroll
            for (int mt = 0; mt < 4; mt++)
                #pragma unroll
                for (int nt = 0; nt < 4; nt++)
                    mma16(acc[mt][nt], af[mt][0], af[mt][1], af[mt][2], af[mt][3],
                          bf[nt][0], bf[nt][1]);
        }
    }
    #undef FILL_A

    #pragma unroll
    for (int mt = 0; mt < 4; mt++) {
        int r = m0 + wm + (mt << 4) + g;
        #pragma unroll
        for (int nt = 0; nt < 4; nt++) {
            int c = n0 + wn + (nt << 3) + (t << 1);
            float2 bv = *(const float2*)(bias + c);
            float o00 = acc[mt][nt][0] + bv.x, o01 = acc[mt][nt][1] + bv.y;
            float o10 = acc[mt][nt][2] + bv.x, o11 = acc[mt][nt][3] + bv.y;
            if (omode == 0) {
                float* C = (float*)Cv;
                *(float2*)(C + (size_t)r       * DIM + c) = make_float2(o00, o01);
                *(float2*)(C + (size_t)(r + 8) * DIM + c) = make_float2(o10, o11);
            } else {
                const float scl = (omode == 2) ? 0.125f : 1.0f;
                __half* C = (__half*)Cv;
                *(__half2*)(C + (size_t)r       * DIM + c) = __floats2half2_rn(o00*scl, o01*scl);
                *(__half2*)(C + (size_t)(r + 8) * DIM + c) = __floats2half2_rn(o10*scl, o11*scl);
            }
        }
    }
}

// ---------------------------------------------------------------------------
// merged q/k/v projection from fp32 inputs: grid (8, 64, 3); z selects set
// ---------------------------------------------------------------------------
__global__ void __launch_bounds__(256,2) gemm_proj(
    const float* __restrict__ Q, const float* __restrict__ K,
    const float* __restrict__ V,
    const float* __restrict__ bq, const float* __restrict__ bk,
    const float* __restrict__ bv)
{
    extern __shared__ __half smh[];
    const unsigned sb = smem_u32(smh);
    const int z = blockIdx.z;
    const float* A    = (z == 0) ? Q  : (z == 1) ? K  : V;
    const float* bias = (z == 0) ? bq : (z == 1) ? bk : bv;
    __half* C = (z == 0) ? g_qh : (z == 1) ? g_kh : g_vh;
    gemm_body<true>(A, g_w[z], bias, C, smh, sb,
                    blockIdx.y << 7, blockIdx.x << 7, (z == 0) ? 2 : 1);
}

// ---------------------------------------------------------------------------
// fused Wo-GEMM + head_reduce fat kernel, INTERLEAVED block mapping:
// even blocks -> GEMM tile (idx>>1), odd blocks -> reduce tile (idx>>1).
// ---------------------------------------------------------------------------
__global__ void __launch_bounds__(256,2) wo_and_weight(
    const float* __restrict__ bo, float* __restrict__ outO,
    float* __restrict__ outW)
{
    extern __shared__ __half smh[];
    const int gidx = blockIdx.x >> 1;
    if ((blockIdx.x & 1) == 0) {
        const unsigned sb = smem_u32(smh);
        gemm_body<false>(g_ohh, g_w[3], bo, outO, smh, sb,
                         (gidx >> 3) << 7, (gidx & 7) << 7, 0);
        return;
    }

    // ---- head_reduce body (tr in dynamic smem: [8][16][66] floats) ----
    float* trb = (float*)smh;
    const int lane = threadIdx.x & 31, warp = threadIdx.x >> 5;
    const int b = gidx >> 7, tile_t = gidx & 127;
    const int r = (lane & 7) + (((lane >> 3) & 1) << 3);
    const int cbase = (lane >> 4) << 3;
    const float invH = 1.0f / (float)HEADS;
    float* tr = trb + warp * 16 * 66;

    for (int ts = warp; ts < SEQ/64; ts += 8) {
        float2 acc[4][4];
        #pragma unroll
        for (int k = 0; k < 4; k++)
            #pragma unroll
            for (int j = 0; j < 4; j++) acc[k][j] = make_float2(0.f, 0.f);

        for (int h = 0; h < HEADS; h++) {
            const int bh = b * HEADS + h;
            const size_t tb4 = ((((size_t)bh*(SEQ/16) + tile_t)*(SEQ/64) + ts)*512) >> 2;
            const uint4* p = (const uint4*)g_expa + tb4 + lane;
            const float rl = __ldg(&g_rl[(size_t)bh*SEQ + (tile_t << 4) + r]);
            #pragma unroll
            for (int k = 0; k < 4; k++) {
                uint4 u = __ldg(p + (k << 5));
                float2 f0 = __half22float2(*(__half2*)&u.x);
                float2 f1 = __half22float2(*(__half2*)&u.y);
                float2 f2 = __half22float2(*(__half2*)&u.z);
                float2 f3 = __half22float2(*(__half2*)&u.w);
                acc[k][0].x += f0.x*rl; acc[k][0].y += f0.y*rl;
                acc[k][1].x += f1.x*rl; acc[k][1].y += f1.y*rl;
                acc[k][2].x += f2.x*rl; acc[k][2].y += f2.y*rl;
                acc[k][3].x += f3.x*rl; acc[k][3].y += f3.y*rl;
            }
        }

        #pragma unroll
        for (int k = 0; k < 4; k++)
            #pragma unroll
            for (int j = 0; j < 4; j++) {
                const int c = cbase + (k << 4) + (j << 1);
                tr[r*66 + c]     = acc[k][j].x * invH;
                tr[r*66 + c + 1] = acc[k][j].y * invH;
            }
        __syncwarp();
        #pragma unroll
        for (int rr = 0; rr < 16; rr++) {
            float2 v = *(float2*)&tr[rr*66 + (lane << 1)];
            *(float2*)(outW + ((size_t)b*SEQ + (tile_t<<4) + rr)*SEQ + (ts<<6) + (lane<<1)) = v;
        }
        __syncwarp();
    }
}

// ---------------------------------------------------------------------------
// attn_o: 8 warps x 16 rows, 2 CTAs/SM. Fragment-blocked coalesced expa.
// (unchanged from round 14)
// ---------------------------------------------------------------------------
#define LDK 72

__global__ void __launch_bounds__(256,2) attn_o_fp16()
{
    __shared__ __half Ks[2][64*LDK];
    __shared__ __half Vs[2][64*LDK];

    const int tid  = threadIdx.x;
    const int lane = tid & 31, warp = tid >> 5;
    const int g = lane >> 2, t = lane & 3;
    const int t0 = blockIdx.x << 7;
    const int bh = blockIdx.y;
    const int b = bh >> 4, h = bh & 15;
    const size_t base = (size_t)b * SEQ * DIM + (size_t)h * HD;
    const __half* qb = g_qh + base;
    const __half* kb = g_kh + base;
    const __half* vb = g_vh + base;
    const int row0 = t0 + (warp << 4) + g;
    const int tile_t = (t0 >> 4) + warp;
    unsigned* ebw = g_expa + ((size_t)bh*(SEQ/16) + tile_t)*(SEQ/64)*512 + lane;

    unsigned qf[4][4];
    #pragma unroll
    for (int ks = 0; ks < 4; ks++) {
        const int c0 = (ks << 4) + (t << 1);
        qf[ks][0] = *(const unsigned*)(qb + (size_t)row0       * DIM + c0);
        qf[ks][1] = *(const unsigned*)(qb + (size_t)(row0 + 8) * DIM + c0);
        qf[ks][2] = *(const unsigned*)(qb + (size_t)row0       * DIM + c0 + 8);
        qf[ks][3] = *(const unsigned*)(qb + (size_t)(row0 + 8) * DIM + c0 + 8);
    }

    float oacc[8][4];
    #pragma unroll
    for (int i = 0; i < 8; i++)
        #pragma unroll
        for (int v = 0; v < 4; v++) oacc[i][v] = 0.f;
    float lp0 = 0.f, lp1 = 0.f;

    const unsigned ksb[2] = { smem_u32(Ks[0]), smem_u32(Ks[1]) };
    const unsigned vsb[2] = { smem_u32(Vs[0]), smem_u32(Vs[1]) };
    const int mi = lane >> 3, mj = lane & 7;

    const int r0c = tid >> 3,         c0c = (tid & 7) << 3;
    const int r1c = (tid + 256) >> 3, c1c = c0c;

    cpa16(ksb[0] + ((r0c*LDK + c0c) << 1), kb + (size_t)r0c * DIM + c0c);
    cpa16(ksb[0] + ((r1c*LDK + c1c) << 1), kb + (size_t)r1c * DIM + c1c);
    cpa16(vsb[0] + ((r0c*LDK + c0c) << 1), vb + (size_t)r0c * DIM + c0c);
    cpa16(vsb[0] + ((r1c*LDK + c1c) << 1), vb + (size_t)r1c * DIM + c1c);
    asm volatile("cp.async.commit_group;\n");

    for (int i = 0; i < SEQ/64; i++) {
        const int st = i & 1;
        if (i + 1 < SEQ/64) {
            const int ns = (i + 1) & 1;
            const size_t nb = (size_t)((i + 1) << 6) * DIM;
            cpa16(ksb[ns] + ((r0c*LDK + c0c) << 1), kb + nb + (size_t)r0c * DIM + c0c);
            cpa16(ksb[ns] + ((r1c*LDK + c1c) << 1), kb + nb + (size_t)r1c * DIM + c1c);
            cpa16(vsb[ns] + ((r0c*LDK + c0c) << 1), vb + nb + (size_t)r0c * DIM + c0c);
            cpa16(vsb[ns] + ((r1c*LDK + c1c) << 1), vb + nb + (size_t)r1c * DIM + c1c);
            asm volatile("cp.async.commit_group;\n");
            asm volatile("cp.async.wait_group 1;\n");
        } else {
            asm volatile("cp.async.wait_group 0;\n");
        }
        __syncthreads();

        const __half* ksp = Ks[st];
        unsigned* eb = ebw + (size_t)i * 512;

        float sc[8][4];
        #pragma unroll
        for (int x = 0; x < 8; x++)
            #pragma unroll
            for (int v = 0; v < 4; v++) sc[x][v] = 0.f;
        #pragma unroll
        for (int ks = 0; ks < 4; ks++) {
            const int kc = (ks << 4) + (t << 1);
            #pragma unroll
            for (int nt = 0; nt < 8; nt++) {
                unsigned b0 = *(const unsigned*)&ksp[((nt<<3)+g)*LDK + kc];
                unsigned b1 = *(const unsigned*)&ksp[((nt<<3)+g)*LDK + kc + 8];
                mma16(sc[nt], qf[ks][0], qf[ks][1], qf[ks][2], qf[ks][3], b0, b1);
            }
        }

        unsigned ph[8][2];
        #pragma unroll
        for (int nt = 0; nt < 8; nt++) {
            float e0 = __expf(fminf(sc[nt][0], 11.f));
            float e1 = __expf(fminf(sc[nt][1], 11.f));
            float e2 = __expf(fminf(sc[nt][2], 11.f));
            float e3 = __expf(fminf(sc[nt][3], 11.f));
            lp0 += e0 + e1;
            lp1 += e2 + e3;
            ph[nt][0] = h2u(__floats2half2_rn(e0, e1));
            ph[nt][1] = h2u(__floats2half2_rn(e2, e3));
            eb[(2*nt    ) << 5] = ph[nt][0];
            eb[(2*nt + 1) << 5] = ph[nt][1];
        }

        #pragma unroll
        for (int ks2 = 0; ks2 < 4; ks2++) {
            const unsigned a0 = ph[2*ks2][0],   a1 = ph[2*ks2][1];
            const unsigned a2 = ph[2*ks2+1][0], a3 = ph[2*ks2+1][1];
            #pragma unroll
            for (int p = 0; p < 4; p++) {
                const int vrow = (ks2 << 4) + ((mi & 1) << 3) + mj;
                const int vcol = (p << 4) + ((mi >> 1) << 3);
                unsigned r[4];
                ldmx4t(r, vsb[st] + (unsigned)((vrow*LDK + vcol) << 1));
                mma16(oacc[2*p],   a0, a1, a2, a3, r[0], r[1]);
                mma16(oacc[2*p+1], a0, a1, a2, a3, r[2], r[3]);
            }
        }
        __syncthreads();
    }

    lp0 += __shfl_xor_sync(0xffffffffu, lp0, 1);
    lp0 += __shfl_xor_sync(0xffffffffu, lp0, 2);
    lp1 += __shfl_xor_sync(0xffffffffu, lp1, 1);
    lp1 += __shfl_xor_sync(0xffffffffu, lp1, 2);
    const float rl0 = 1.0f / lp0;
    const float rl1 = 1.0f / lp1;
    if (t == 0) {
        g_rl[(size_t)bh * SEQ + row0]     = rl0;
        g_rl[(size_t)bh * SEQ + row0 + 8] = rl1;
    }
    #pragma unroll
    for (int nt = 0; nt < 8; nt++) {
        const int c = h*HD + (nt << 3) + (t << 1);
        *(__half2*)(g_ohh + (size_t)(b*SEQ + row0)     * DIM + c) =
            __floats2half2_rn(oacc[nt][0]*rl0, oacc[nt][1]*rl0);
        *(__half2*)(g_ohh + (size_t)(b*SEQ + row0 + 8) * DIM + c) =
            __floats2half2_rn(oacc[nt][2]*rl1, oacc[nt][3]*rl1);
    }
}

// ---------------------------------------------------------------------------
extern "C" void kernel_launch(void* const* d_in, const int* in_sizes, int n_in,
                              void* d_out, int out_size)
{
    const float* Q  = (const float*)d_in[0];
    const float* K  = (const float*)d_in[1];
    const float* V  = (const float*)d_in[2];
    const float* Wq = (const float*)d_in[3];
    const float* bq = (const float*)d_in[4];
    const float* Wk = (const float*)d_in[5];
    const float* bk = (const float*)d_in[6];
    const float* Wv = (const float*)d_in[7];
    const float* bv = (const float*)d_in[8];
    const float* Wo = (const float*)d_in[9];
    const float* bo = (const float*)d_in[10];

    float* outO = (float*)d_out;                       // [B,T,D]
    float* outW = outO + (size_t)BATCH * SEQ * DIM;    // [B,T,T]

    cudaFuncSetAttribute(gemm_proj,     cudaFuncAttributeMaxDynamicSharedMemorySize, G_SMEM_BYTES);
    cudaFuncSetAttribute(wo_and_weight, cudaFuncAttributeMaxDynamicSharedMemorySize, G_SMEM_BYTES);

    // weight-only fp32->fp16 conversion (inputs converted inline in gemm_proj)
    cvt_w<<<dim3(128, 4), 256>>>(Wq, Wk, Wv, Wo);

    // merged q/k/v projections from fp32 inputs: grid (8, 64, 3)
    gemm_proj<<<dim3(DIM/128, MTOT/128, 3), 256, G_SMEM_BYTES>>>(Q, K, V, bq, bk, bv);

    attn_o_fp16<<<dim3(SEQ/128, BATCH*HEADS), 256>>>();

    // fused+interleaved Wo-GEMM (even blocks) + head_reduce (odd blocks)
    wo_and_weight<<<1024, 256, G_SMEM_BYTES>>>(bo, outO, outW);
}

// round 16
// speedup vs baseline: 1.0733x; 1.0733x over previous
#include <cuda_runtime.h>
#include <cuda_fp16.h>
#include <cstdint>
#include <math.h>

#define BATCH 4
#define SEQ   2048
#define DIM   1024
#define HEADS 16
#define HD    64
#define MTOT  (BATCH*SEQ)   // 8192

// Scratch (allocation-free rule: __device__ globals)
__device__ __half g_in [3][MTOT*DIM];     // fp16 copies of Q,K,V inputs
__device__ __half g_w  [4][DIM*DIM];      // fp16 copies of Wq,Wk,Wv,Wo
__device__ __half g_qh [MTOT*DIM];        // projected q (pre-scaled 0.125)
__device__ __half g_kh [MTOT*DIM];
__device__ __half g_vh [MTOT*DIM];
__device__ __half g_ohh[MTOT*DIM];        // attention output heads
__device__ float  g_rl [BATCH*HEADS*SEQ];
// exp(scores), FRAGMENT-BLOCKED: tile (bh,tile_t,tile_s) of 16x64 halves
// = 512 words; word addr = tile*512 + word_idx*32 + lane.
__device__ unsigned g_expa[(size_t)BATCH*HEADS*(SEQ/16)*(SEQ/64)*512];

// ---------------------------------------------------------------------------
// helpers
// ---------------------------------------------------------------------------
__device__ __forceinline__ void mma16(float c[4],
    unsigned a0, unsigned a1, unsigned a2, unsigned a3,
    unsigned b0, unsigned b1)
{
    asm volatile(
      "mma.sync.aligned.m16n8k16.row.col.f32.f16.f16.f32 "
      "{%0,%1,%2,%3},{%4,%5,%6,%7},{%8,%9},{%0,%1,%2,%3};"
      : "+f"(c[0]), "+f"(c[1]), "+f"(c[2]), "+f"(c[3])
      : "r"(a0), "r"(a1), "r"(a2), "r"(a3), "r"(b0), "r"(b1));
}
__device__ __forceinline__ void ldmx4(unsigned r[4], unsigned addr)
{
    asm volatile(
      "ldmatrix.sync.aligned.m8n8.x4.shared.b16 {%0,%1,%2,%3}, [%4];"
      : "=r"(r[0]), "=r"(r[1]), "=r"(r[2]), "=r"(r[3]) : "r"(addr));
}
__device__ __forceinline__ void ldmx4t(unsigned r[4], unsigned addr)
{
    asm volatile(
      "ldmatrix.sync.aligned.m8n8.x4.trans.shared.b16 {%0,%1,%2,%3}, [%4];"
      : "=r"(r[0]), "=r"(r[1]), "=r"(r[2]), "=r"(r[3]) : "r"(addr));
}
__device__ __forceinline__ unsigned h2u(__half2 h) { return *(unsigned*)&h; }
__device__ __forceinline__ void cpa16(unsigned dst, const void* src) {
    asm volatile("cp.async.cg.shared.global [%0], [%1], 16;\n" :: "r"(dst), "l"(src));
}
__device__ __forceinline__ uint32_t smem_u32(const void* p) {
    uint32_t a;
    asm("{ .reg .u64 t; cvta.to.shared.u64 t, %1; cvt.u32.u64 %0, t; }"
        : "=r"(a) : "l"(p));
    return a;
}

// ---------------------------------------------------------------------------
// single fp32->fp16 convert covering all 7 tensors (grid.y selects).
// Wide grid (1024 x-blocks) -> high MLP; round-7 showed the narrow version
// was latency-bound at 8.8% DRAM.
// ---------------------------------------------------------------------------
__global__ void __launch_bounds__(256) cvt_all(
    const float* q, const float* k, const float* v,
    const float* wq, const float* wk, const float* wv, const float* wo)
{
    const int y = blockIdx.y;
    const float* src;
    __half* dst;
    int n4;
    switch (y) {
        case 0: src = q;  dst = g_in[0]; n4 = MTOT*DIM/4; break;
        case 1: src = k;  dst = g_in[1]; n4 = MTOT*DIM/4; break;
        case 2: src = v;  dst = g_in[2]; n4 = MTOT*DIM/4; break;
        case 3: src = wq; dst = g_w[0];  n4 = DIM*DIM/4;  break;
        case 4: src = wk; dst = g_w[1];  n4 = DIM*DIM/4;  break;
        case 5: src = wv; dst = g_w[2];  n4 = DIM*DIM/4;  break;
        default: src = wo; dst = g_w[3]; n4 = DIM*DIM/4;  break;
    }
    for (int i = blockIdx.x*256 + threadIdx.x; i < n4; i += gridDim.x*256) {
        float4 f = *(const float4*)(src + (size_t)i*4);
        *(__half2*)(dst + (size_t)i*4)     = __floats2half2_rn(f.x, f.y);
        *(__half2*)(dst + (size_t)i*4 + 2) = __floats2half2_rn(f.z, f.w);
    }
}

// ---------------------------------------------------------------------------
// fp16 NT GEMM body, 4-stage cp.async pipeline, one barrier per k-tile.
// Block tile 128x128, BK=32, 256 threads, warp tile 64x32.
// omode: 0 fp32-out, 1 fp16-out, 2 fp16-out scaled 0.125.
// ---------------------------------------------------------------------------
#define LDH   40
#define G_STB (128*LDH)                 // halves per stage-operand (10240 B)
#define G_SMEM_BYTES (4 * 2 * G_STB * 2)  // 81920

__device__ __forceinline__ void gemm_body(
    const __half* __restrict__ A, const __half* __restrict__ W,
    const float* __restrict__ bias, void* __restrict__ Cv,
    unsigned sb, int m0, int n0, int omode)
{
    const int tid  = threadIdx.x;
    const int lane = tid & 31, warp = tid >> 5;
    const int g = lane >> 2, t = lane & 3;
    const int wm = (warp >> 2) << 6, wn = (warp & 3) << 5;
    const __half* Ab = A + (size_t)m0 * DIM;
    const __half* Wb = W + (size_t)n0 * DIM;

    const int ch0 = tid << 1, ch1 = ch0 + 1;
    const int r0 = ch0 >> 2, c0 = (ch0 & 3) << 3;
    const int r1 = ch1 >> 2, c1 = (ch1 & 3) << 3;
    const unsigned aOff0 = (unsigned)((r0*LDH + c0) << 1);
    const unsigned aOff1 = (unsigned)((r1*LDH + c1) << 1);

    const int aRow = wm + (lane & 15);
    const int aKof = (lane >> 4) << 3;
    const int bRow = wn + ((lane >> 4) << 3) + (lane & 7);
    const int bKof = ((lane >> 3) & 1) << 3;

    float acc[4][4][4];
    #pragma unroll
    for (int i = 0; i < 4; i++)
        #pragma unroll
        for (int j = 0; j < 4; j++)
            #pragma unroll
            for (int v = 0; v < 4; v++) acc[i][j][v] = 0.f;

    #pragma unroll
    for (int s = 0; s < 3; s++) {
        const unsigned stB = (unsigned)(s * 2 * G_STB) << 1;
        const int k0 = s << 5;
        cpa16(sb + stB + aOff0,                    Ab + (size_t)r0 * DIM + k0 + c0);
        cpa16(sb + stB + aOff1,                    Ab + (size_t)r1 * DIM + k0 + c1);
        cpa16(sb + stB + (G_STB << 1) + aOff0,     Wb + (size_t)r0 * DIM + k0 + c0);
        cpa16(sb + stB + (G_STB << 1) + aOff1,     Wb + (size_t)r1 * DIM + k0 + c1);
        asm volatile("cp.async.commit_group;\n");
    }

    for (int kt = 0; kt < 32; kt++) {
        if (kt <= 29)      asm volatile("cp.async.wait_group 2;\n");
        else if (kt == 30) asm volatile("cp.async.wait_group 1;\n");
        else               asm volatile("cp.async.wait_group 0;\n");
        __syncthreads();

        if (kt + 3 < 32) {
            const int s = (kt + 3) & 3;
            const unsigned stB = (unsigned)(s * 2 * G_STB) << 1;
            const int k0 = (kt + 3) << 5;
            cpa16(sb + stB + aOff0,                Ab + (size_t)r0 * DIM + k0 + c0);
            cpa16(sb + stB + aOff1,                Ab + (size_t)r1 * DIM + k0 + c1);
            cpa16(sb + stB + (G_STB << 1) + aOff0, Wb + (size_t)r0 * DIM + k0 + c0);
            cpa16(sb + stB + (G_STB << 1) + aOff1, Wb + (size_t)r1 * DIM + k0 + c1);
            asm volatile("cp.async.commit_group;\n");
        }

        const unsigned aB = sb + ((unsigned)((kt & 3) * 2 * G_STB) << 1);
        const unsigned wB = aB + (G_STB << 1);
        #pragma unroll
        for (int s = 0; s < 2; s++) {
            const int kh = s << 4;
            unsigned af[4][4], bf[4][2];
            #pragma unroll
            for (int mt = 0; mt < 4; mt++)
                ldmx4(af[mt], aB +
                      (unsigned)(((aRow + (mt << 4))*LDH + kh + aKof) << 1));
            #pragma unroll
            for (int p = 0; p < 2; p++) {
                unsigned bx[4];
                ldmx4(bx, wB +
                      (unsigned)(((bRow + (p << 4))*LDH + kh + bKof) << 1));
                bf[2*p][0]   = bx[0]; bf[2*p][1]   = bx[1];
                bf[2*p+1][0] = bx[2]; bf[2*p+1][1] = bx[3];
            }
            #pragma unroll
            for (int mt = 0; mt < 4; mt++)
                #pragma unroll
                for (int nt = 0; nt < 4; nt++)
                    mma16(acc[mt][nt], af[mt][0], af[mt][1], af[mt][2], af[mt][3],
                          bf[nt][0], bf[nt][1]);
        }
    }

    #pragma unroll
    for (int mt = 0; mt < 4; mt++) {
        int r = m0 + wm + (mt << 4) + g;
        #pragma unroll
        for (int nt = 0; nt < 4; nt++) {
            int c = n0 + wn + (nt << 3) + (t << 1);
            float2 bv = *(const float2*)(bias + c);
            float o00 = acc[mt][nt][0] + bv.x, o01 = acc[mt][nt][1] + bv.y;
            float o10 = acc[mt][nt][2] + bv.x, o11 = acc[mt][nt][3] + bv.y;
            if (omode == 0) {
                float* C = (float*)Cv;
                *(float2*)(C + (size_t)r       * DIM + c) = make_float2(o00, o01);
                *(float2*)(C + (size_t)(r + 8) * DIM + c) = make_float2(o10, o11);
            } else {
                const float scl = (omode == 2) ? 0.125f : 1.0f;
                __half* C = (__half*)Cv;
                *(__half2*)(C + (size_t)r       * DIM + c) = __floats2half2_rn(o00*scl, o01*scl);
                *(__half2*)(C + (size_t)(r + 8) * DIM + c) = __floats2half2_rn(o10*scl, o11*scl);
            }
        }
    }
}

// ---------------------------------------------------------------------------
// merged q/k/v projection: grid (8, 64, 3); z selects tensor set
// ---------------------------------------------------------------------------
__global__ void __launch_bounds__(256,2) gemm_proj(
    const float* __restrict__ bq, const float* __restrict__ bk,
    const float* __restrict__ bv)
{
    extern __shared__ __half smh[];
    const unsigned sb = smem_u32(smh);
    const int z = blockIdx.z;
    const float* bias = (z == 0) ? bq : (z == 1) ? bk : bv;
    __half* C = (z == 0) ? g_qh : (z == 1) ? g_kh : g_vh;
    gemm_body(g_in[z], g_w[z], bias, C, sb,
              blockIdx.y << 7, blockIdx.x << 7, (z == 0) ? 2 : 1);
}

// ---------------------------------------------------------------------------
// fused Wo-GEMM + head_reduce fat kernel, INTERLEAVED block mapping:
// even blocks -> GEMM tile (idx>>1), odd blocks -> reduce tile (idx>>1).
// ---------------------------------------------------------------------------
__global__ void __launch_bounds__(256,2) wo_and_weight(
    const float* __restrict__ bo, float* __restrict__ outO,
    float* __restrict__ outW)
{
    extern __shared__ __half smh[];
    const int gidx = blockIdx.x >> 1;
    if ((blockIdx.x & 1) == 0) {
        const unsigned sb = smem_u32(smh);
        gemm_body(g_ohh, g_w[3], bo, outO, sb,
                  (gidx >> 3) << 7, (gidx & 7) << 7, 0);
        return;
    }

    // ---- head_reduce body (tr in dynamic smem: [8][16][66] floats) ----
    float* trb = (float*)smh;
    const int lane = threadIdx.x & 31, warp = threadIdx.x >> 5;
    const int b = gidx >> 7, tile_t = gidx & 127;
    const int r = (lane & 7) + (((lane >> 3) & 1) << 3);
    const int cbase = (lane >> 4) << 3;
    const float invH = 1.0f / (float)HEADS;
    float* tr = trb + warp * 16 * 66;

    for (int ts = warp; ts < SEQ/64; ts += 8) {
        float2 acc[4][4];
        #pragma unroll
        for (int k = 0; k < 4; k++)
            #pragma unroll
            for (int j = 0; j < 4; j++) acc[k][j] = make_float2(0.f, 0.f);

        for (int h = 0; h < HEADS; h++) {
            const int bh = b * HEADS + h;
            const size_t tb4 = ((((size_t)bh*(SEQ/16) + tile_t)*(SEQ/64) + ts)*512) >> 2;
            const uint4* p = (const uint4*)g_expa + tb4 + lane;
            const float rl = __ldg(&g_rl[(size_t)bh*SEQ + (tile_t << 4) + r]);
            #pragma unroll
            for (int k = 0; k < 4; k++) {
                uint4 u = __ldg(p + (k << 5));
                float2 f0 = __half22float2(*(__half2*)&u.x);
                float2 f1 = __half22float2(*(__half2*)&u.y);
                float2 f2 = __half22float2(*(__half2*)&u.z);
                float2 f3 = __half22float2(*(__half2*)&u.w);
                acc[k][0].x += f0.x*rl; acc[k][0].y += f0.y*rl;
                acc[k][1].x += f1.x*rl; acc[k][1].y += f1.y*rl;
                acc[k][2].x += f2.x*rl; acc[k][2].y += f2.y*rl;
                acc[k][3].x += f3.x*rl; acc[k][3].y += f3.y*rl;
            }
        }

        #pragma unroll
        for (int k = 0; k < 4; k++)
            #pragma unroll
            for (int j = 0; j < 4; j++) {
                const int c = cbase + (k << 4) + (j << 1);
                tr[r*66 + c]     = acc[k][j].x * invH;
                tr[r*66 + c + 1] = acc[k][j].y * invH;
            }
        __syncwarp();
        #pragma unroll
        for (int rr = 0; rr < 16; rr++) {
            float2 v = *(float2*)&tr[rr*66 + (lane << 1)];
            *(float2*)(outW + ((size_t)b*SEQ + (tile_t<<4) + rr)*SEQ + (ts<<6) + (lane<<1)) = v;
        }
        __syncwarp();
    }
}

// ---------------------------------------------------------------------------
// attn_o: 8 warps x 16 rows, 2 CTAs/SM. Fragment-blocked coalesced expa.
// ---------------------------------------------------------------------------
#define LDK 72

__global__ void __launch_bounds__(256,2) attn_o_fp16()
{
    __shared__ __half Ks[2][64*LDK];
    __shared__ __half Vs[2][64*LDK];

    const int tid  = threadIdx.x;
    const int lane = tid & 31, warp = tid >> 5;
    const int g = lane >> 2, t = lane & 3;
    const int t0 = blockIdx.x << 7;                 // 128 rows per block
    const int bh = blockIdx.y;
    const int b = bh >> 4, h = bh & 15;
    const size_t base = (size_t)b * SEQ * DIM + (size_t)h * HD;
    const __half* qb = g_qh + base;
    const __half* kb = g_kh + base;
    const __half* vb = g_vh + base;
    const int row0 = t0 + (warp << 4) + g;
    const int tile_t = (t0 >> 4) + warp;
    unsigned* ebw = g_expa + ((size_t)bh*(SEQ/16) + tile_t)*(SEQ/64)*512 + lane;

    unsigned qf[4][4];
    #pragma unroll
    for (int ks = 0; ks < 4; ks++) {
        const int c0 = (ks << 4) + (t << 1);
        qf[ks][0] = *(const unsigned*)(qb + (size_t)row0       * DIM + c0);
        qf[ks][1] = *(const unsigned*)(qb + (size_t)(row0 + 8) * DIM + c0);
        qf[ks][2] = *(const unsigned*)(qb + (size_t)row0       * DIM + c0 + 8);
        qf[ks][3] = *(const unsigned*)(qb + (size_t)(row0 + 8) * DIM + c0 + 8);
    }

    float oacc[8][4];
    #pragma unroll
    for (int i = 0; i < 8; i++)
        #pragma unroll
        for (int v = 0; v < 4; v++) oacc[i][v] = 0.f;
    float lp0 = 0.f, lp1 = 0.f;

    const unsigned ksb[2] = { smem_u32(Ks[0]), smem_u32(Ks[1]) };
    const unsigned vsb[2] = { smem_u32(Vs[0]), smem_u32(Vs[1]) };
    const int mi = lane >> 3, mj = lane & 7;

    const int r0c = tid >> 3,         c0c = (tid & 7) << 3;
    const int r1c = (tid + 256) >> 3, c1c = c0c;

    cpa16(ksb[0] + ((r0c*LDK + c0c) << 1), kb + (size_t)r0c * DIM + c0c);
    cpa16(ksb[0] + ((r1c*LDK + c1c) << 1), kb + (size_t)r1c * DIM + c1c);
    cpa16(vsb[0] + ((r0c*LDK + c0c) << 1), vb + (size_t)r0c * DIM + c0c);
    cpa16(vsb[0] + ((r1c*LDK + c1c) << 1), vb + (size_t)r1c * DIM + c1c);
    asm volatile("cp.async.commit_group;\n");

    for (int i = 0; i < SEQ/64; i++) {
        const int st = i & 1;
        if (i + 1 < SEQ/64) {
            const int ns = (i + 1) & 1;
            const size_t nb = (size_t)((i + 1) << 6) * DIM;
            cpa16(ksb[ns] + ((r0c*LDK + c0c) << 1), kb + nb + (size_t)r0c * DIM + c0c);
            cpa16(ksb[ns] + ((r1c*LDK + c1c) << 1), kb + nb + (size_t)r1c * DIM + c1c);
            cpa16(vsb[ns] + ((r0c*LDK + c0c) << 1), vb + nb + (size_t)r0c * DIM + c0c);
            cpa16(vsb[ns] + ((r1c*LDK + c1c) << 1), vb + nb + (size_t)r1c * DIM + c1c);
            asm volatile("cp.async.commit_group;\n");
            asm volatile("cp.async.wait_group 1;\n");
        } else {
            asm volatile("cp.async.wait_group 0;\n");
        }
        __syncthreads();

        const __half* ksp = Ks[st];
        unsigned* eb = ebw + (size_t)i * 512;

        float sc[8][4];
        #pragma unroll
        for (int x = 0; x < 8; x++)
            #pragma unroll
            for (int v = 0; v < 4; v++) sc[x][v] = 0.f;
        #pragma unroll
        for (int ks = 0; ks < 4; ks++) {
            const int kc = (ks << 4) + (t << 1);
            #pragma unroll
            for (int nt = 0; nt < 8; nt++) {
                unsigned b0 = *(const unsigned*)&ksp[((nt<<3)+g)*LDK + kc];
                unsigned b1 = *(const unsigned*)&ksp[((nt<<3)+g)*LDK + kc + 8];
                mma16(sc[nt], qf[ks][0], qf[ks][1], qf[ks][2], qf[ks][3], b0, b1);
            }
        }

        unsigned ph[8][2];
        #pragma unroll
        for (int nt = 0; nt < 8; nt++) {
            float e0 = __expf(fminf(sc[nt][0], 11.f));
            float e1 = __expf(fminf(sc[nt][1], 11.f));
            float e2 = __expf(fminf(sc[nt][2], 11.f));
            float e3 = __expf(fminf(sc[nt][3], 11.f));
            lp0 += e0 + e1;
            lp1 += e2 + e3;
            ph[nt][0] = h2u(__floats2half2_rn(e0, e1));
            ph[nt][1] = h2u(__floats2half2_rn(e2, e3));
            eb[(2*nt    ) << 5] = ph[nt][0];
            eb[(2*nt + 1) << 5] = ph[nt][1];
        }

        #pragma unroll
        for (int ks2 = 0; ks2 < 4; ks2++) {
            const unsigned a0 = ph[2*ks2][0],   a1 = ph[2*ks2][1];
            const unsigned a2 = ph[2*ks2+1][0], a3 = ph[2*ks2+1][1];
            #pragma unroll
            for (int p = 0; p < 4; p++) {
                const int vrow = (ks2 << 4) + ((mi & 1) << 3) + mj;
                const int vcol = (p << 4) + ((mi >> 1) << 3);
                unsigned r[4];
                ldmx4t(r, vsb[st] + (unsigned)((vrow*LDK + vcol) << 1));
                mma16(oacc[2*p],   a0, a1, a2, a3, r[0], r[1]);
                mma16(oacc[2*p+1], a0, a1, a2, a3, r[2], r[3]);
            }
        }
        __syncthreads();
    }

    lp0 += __shfl_xor_sync(0xffffffffu, lp0, 1);
    lp0 += __shfl_xor_sync(0xffffffffu, lp0, 2);
    lp1 += __shfl_xor_sync(0xffffffffu, lp1, 1);
    lp1 += __shfl_xor_sync(0xffffffffu, lp1, 2);
    const float rl0 = 1.0f / lp0;
    const float rl1 = 1.0f / lp1;
    if (t == 0) {
        g_rl[(size_t)bh * SEQ + row0]     = rl0;
        g_rl[(size_t)bh * SEQ + row0 + 8] = rl1;
    }
    #pragma unroll
    for (int nt = 0; nt < 8; nt++) {
        const int c = h*HD + (nt << 3) + (t << 1);
        *(__half2*)(g_ohh + (size_t)(b*SEQ + row0)     * DIM + c) =
            __floats2half2_rn(oacc[nt][0]*rl0, oacc[nt][1]*rl0);
        *(__half2*)(g_ohh + (size_t)(b*SEQ + row0 + 8) * DIM + c) =
            __floats2half2_rn(oacc[nt][2]*rl1, oacc[nt][3]*rl1);
    }
}

// ---------------------------------------------------------------------------
extern "C" void kernel_launch(void* const* d_in, const int* in_sizes, int n_in,
                              void* d_out, int out_size)
{
    const float* Q  = (const float*)d_in[0];
    const float* K  = (const float*)d_in[1];
    const float* V  = (const float*)d_in[2];
    const float* Wq = (const float*)d_in[3];
    const float* bq = (const float*)d_in[4];
    const float* Wk = (const float*)d_in[5];
    const float* bk = (const float*)d_in[6];
    const float* Wv = (const float*)d_in[7];
    const float* bv = (const float*)d_in[8];
    const float* Wo = (const float*)d_in[9];
    const float* bo = (const float*)d_in[10];

    float* outO = (float*)d_out;                       // [B,T,D]
    float* outW = outO + (size_t)BATCH * SEQ * DIM;    // [B,T,T]

    cudaFuncSetAttribute(gemm_proj,     cudaFuncAttributeMaxDynamicSharedMemorySize, G_SMEM_BYTES);
    cudaFuncSetAttribute(wo_and_weight, cudaFuncAttributeMaxDynamicSharedMemorySize, G_SMEM_BYTES);

    // wide grid: cvt is latency-bound at narrow grids (round-7 ncu)
    cvt_all<<<dim3(1024, 7), 256>>>(Q, K, V, Wq, Wk, Wv, Wo);

    // merged q/k/v projections: grid (8, 64, 3)
    gemm_proj<<<dim3(DIM/128, MTOT/128, 3), 256, G_SMEM_BYTES>>>(bq, bk, bv);

    attn_o_fp16<<<dim3(SEQ/128, BATCH*HEADS), 256>>>();

    // fused+interleaved Wo-GEMM (even blocks) + head_reduce (odd blocks)
    wo_and_weight<<<1024, 256, G_SMEM_BYTES>>>(bo, outO, outW);
}

// round 17
// speedup vs baseline: 1.0739x; 1.0006x over previous
#include <cuda_runtime.h>
#include <cuda_fp16.h>
#include <cstdint>
#include <math.h>

#define BATCH 4
#define SEQ   2048
#define DIM   1024
#define HEADS 16
#define HD    64
#define MTOT  (BATCH*SEQ)   // 8192

// Scratch (allocation-free rule: __device__ globals)
__device__ __half g_in [3][MTOT*DIM];     // fp16 copies of Q,K,V inputs
__device__ __half g_w  [4][DIM*DIM];      // fp16 copies of Wq,Wk,Wv,Wo
__device__ __half g_qh [MTOT*DIM];        // projected q (pre-scaled 0.125)
__device__ __half g_kh [MTOT*DIM];
__device__ __half g_vh [MTOT*DIM];
__device__ __half g_ohh[MTOT*DIM];        // attention output heads
__device__ float  g_rl [BATCH*HEADS*SEQ];
// exp(scores), FRAGMENT-BLOCKED: tile (bh,tile_t,tile_s) of 16x64 halves
// = 512 words; word addr = tile*512 + word_idx*32 + lane.
__device__ unsigned g_expa[(size_t)BATCH*HEADS*(SEQ/16)*(SEQ/64)*512];

// ---------------------------------------------------------------------------
// helpers
// ---------------------------------------------------------------------------
__device__ __forceinline__ void mma16(float c[4],
    unsigned a0, unsigned a1, unsigned a2, unsigned a3,
    unsigned b0, unsigned b1)
{
    asm volatile(
      "mma.sync.aligned.m16n8k16.row.col.f32.f16.f16.f32 "
      "{%0,%1,%2,%3},{%4,%5,%6,%7},{%8,%9},{%0,%1,%2,%3};"
      : "+f"(c[0]), "+f"(c[1]), "+f"(c[2]), "+f"(c[3])
      : "r"(a0), "r"(a1), "r"(a2), "r"(a3), "r"(b0), "r"(b1));
}
__device__ __forceinline__ void ldmx4(unsigned r[4], unsigned addr)
{
    asm volatile(
      "ldmatrix.sync.aligned.m8n8.x4.shared.b16 {%0,%1,%2,%3}, [%4];"
      : "=r"(r[0]), "=r"(r[1]), "=r"(r[2]), "=r"(r[3]) : "r"(addr));
}
__device__ __forceinline__ void ldmx4t(unsigned r[4], unsigned addr)
{
    asm volatile(
      "ldmatrix.sync.aligned.m8n8.x4.trans.shared.b16 {%0,%1,%2,%3}, [%4];"
      : "=r"(r[0]), "=r"(r[1]), "=r"(r[2]), "=r"(r[3]) : "r"(addr));
}
__device__ __forceinline__ unsigned h2u(__half2 h) { return *(unsigned*)&h; }
__device__ __forceinline__ void cpa16(unsigned dst, const void* src) {
    asm volatile("cp.async.cg.shared.global [%0], [%1], 16;\n" :: "r"(dst), "l"(src));
}
__device__ __forceinline__ uint32_t smem_u32(const void* p) {
    uint32_t a;
    asm("{ .reg .u64 t; cvta.to.shared.u64 t, %1; cvt.u32.u64 %0, t; }"
        : "=r"(a) : "l"(p));
    return a;
}

// ---------------------------------------------------------------------------
// single fp32->fp16 convert covering all 7 tensors (grid.y selects), wide grid
// ---------------------------------------------------------------------------
__global__ void __launch_bounds__(256) cvt_all(
    const float* q, const float* k, const float* v,
    const float* wq, const float* wk, const float* wv, const float* wo)
{
    const int y = blockIdx.y;
    const float* src;
    __half* dst;
    int n4;
    switch (y) {
        case 0: src = q;  dst = g_in[0]; n4 = MTOT*DIM/4; break;
        case 1: src = k;  dst = g_in[1]; n4 = MTOT*DIM/4; break;
        case 2: src = v;  dst = g_in[2]; n4 = MTOT*DIM/4; break;
        case 3: src = wq; dst = g_w[0];  n4 = DIM*DIM/4;  break;
        case 4: src = wk; dst = g_w[1];  n4 = DIM*DIM/4;  break;
        case 5: src = wv; dst = g_w[2];  n4 = DIM*DIM/4;  break;
        default: src = wo; dst = g_w[3]; n4 = DIM*DIM/4;  break;
    }
    for (int i = blockIdx.x*256 + threadIdx.x; i < n4; i += gridDim.x*256) {
        float4 f = *(const float4*)(src + (size_t)i*4);
        *(__half2*)(dst + (size_t)i*4)     = __floats2half2_rn(f.x, f.y);
        *(__half2*)(dst + (size_t)i*4 + 2) = __floats2half2_rn(f.z, f.w);
    }
}

// ---------------------------------------------------------------------------
// fp16 NT GEMM body, 4-stage cp.async pipeline, one barrier per k-tile.
// ---------------------------------------------------------------------------
#define LDH   40
#define G_STB (128*LDH)                 // halves per stage-operand (10240 B)
#define G_SMEM_BYTES (4 * 2 * G_STB * 2)  // 81920

__device__ __forceinline__ void gemm_body(
    const __half* __restrict__ A, const __half* __restrict__ W,
    const float* __restrict__ bias, void* __restrict__ Cv,
    unsigned sb, int m0, int n0, int omode)
{
    const int tid  = threadIdx.x;
    const int lane = tid & 31, warp = tid >> 5;
    const int g = lane >> 2, t = lane & 3;
    const int wm = (warp >> 2) << 6, wn = (warp & 3) << 5;
    const __half* Ab = A + (size_t)m0 * DIM;
    const __half* Wb = W + (size_t)n0 * DIM;

    const int ch0 = tid << 1, ch1 = ch0 + 1;
    const int r0 = ch0 >> 2, c0 = (ch0 & 3) << 3;
    const int r1 = ch1 >> 2, c1 = (ch1 & 3) << 3;
    const unsigned aOff0 = (unsigned)((r0*LDH + c0) << 1);
    const unsigned aOff1 = (unsigned)((r1*LDH + c1) << 1);

    const int aRow = wm + (lane & 15);
    const int aKof = (lane >> 4) << 3;
    const int bRow = wn + ((lane >> 4) << 3) + (lane & 7);
    const int bKof = ((lane >> 3) & 1) << 3;

    float acc[4][4][4];
    #pragma unroll
    for (int i = 0; i < 4; i++)
        #pragma unroll
        for (int j = 0; j < 4; j++)
            #pragma unroll
            for (int v = 0; v < 4; v++) acc[i][j][v] = 0.f;

    #pragma unroll
    for (int s = 0; s < 3; s++) {
        const unsigned stB = (unsigned)(s * 2 * G_STB) << 1;
        const int k0 = s << 5;
        cpa16(sb + stB + aOff0,                    Ab + (size_t)r0 * DIM + k0 + c0);
        cpa16(sb + stB + aOff1,                    Ab + (size_t)r1 * DIM + k0 + c1);
        cpa16(sb + stB + (G_STB << 1) + aOff0,     Wb + (size_t)r0 * DIM + k0 + c0);
        cpa16(sb + stB + (G_STB << 1) + aOff1,     Wb + (size_t)r1 * DIM + k0 + c1);
        asm volatile("cp.async.commit_group;\n");
    }

    for (int kt = 0; kt < 32; kt++) {
        if (kt <= 29)      asm volatile("cp.async.wait_group 2;\n");
        else if (kt == 30) asm volatile("cp.async.wait_group 1;\n");
        else               asm volatile("cp.async.wait_group 0;\n");
        __syncthreads();

        if (kt + 3 < 32) {
            const int s = (kt + 3) & 3;
            const unsigned stB = (unsigned)(s * 2 * G_STB) << 1;
            const int k0 = (kt + 3) << 5;
            cpa16(sb + stB + aOff0,                Ab + (size_t)r0 * DIM + k0 + c0);
            cpa16(sb + stB + aOff1,                Ab + (size_t)r1 * DIM + k0 + c1);
            cpa16(sb + stB + (G_STB << 1) + aOff0, Wb + (size_t)r0 * DIM + k0 + c0);
            cpa16(sb + stB + (G_STB << 1) + aOff1, Wb + (size_t)r1 * DIM + k0 + c1);
            asm volatile("cp.async.commit_group;\n");
        }

        const unsigned aB = sb + ((unsigned)((kt & 3) * 2 * G_STB) << 1);
        const unsigned wB = aB + (G_STB << 1);
        #pragma unroll
        for (int s = 0; s < 2; s++) {
            const int kh = s << 4;
            unsigned af[4][4], bf[4][2];
            #pragma unroll
            for (int mt = 0; mt < 4; mt++)
                ldmx4(af[mt], aB +
                      (unsigned)(((aRow + (mt << 4))*LDH + kh + aKof) << 1));
            #pragma unroll
            for (int p = 0; p < 2; p++) {
                unsigned bx[4];
                ldmx4(bx, wB +
                      (unsigned)(((bRow + (p << 4))*LDH + kh + bKof) << 1));
                bf[2*p][0]   = bx[0]; bf[2*p][1]   = bx[1];
                bf[2*p+1][0] = bx[2]; bf[2*p+1][1] = bx[3];
            }
            #pragma unroll
            for (int mt = 0; mt < 4; mt++)
                #pragma unroll
                for (int nt = 0; nt < 4; nt++)
                    mma16(acc[mt][nt], af[mt][0], af[mt][1], af[mt][2], af[mt][3],
                          bf[nt][0], bf[nt][1]);
        }
    }

    #pragma unroll
    for (int mt = 0; mt < 4; mt++) {
        int r = m0 + wm + (mt << 4) + g;
        #pragma unroll
        for (int nt = 0; nt < 4; nt++) {
            int c = n0 + wn + (nt << 3) + (t << 1);
            float2 bv = *(const float2*)(bias + c);
            float o00 = acc[mt][nt][0] + bv.x, o01 = acc[mt][nt][1] + bv.y;
            float o10 = acc[mt][nt][2] + bv.x, o11 = acc[mt][nt][3] + bv.y;
            if (omode == 0) {
                float* C = (float*)Cv;
                *(float2*)(C + (size_t)r       * DIM + c) = make_float2(o00, o01);
                *(float2*)(C + (size_t)(r + 8) * DIM + c) = make_float2(o10, o11);
            } else {
                const float scl = (omode == 2) ? 0.125f : 1.0f;
                __half* C = (__half*)Cv;
                *(__half2*)(C + (size_t)r       * DIM + c) = __floats2half2_rn(o00*scl, o01*scl);
                *(__half2*)(C + (size_t)(r + 8) * DIM + c) = __floats2half2_rn(o10*scl, o11*scl);
            }
        }
    }
}

// ---------------------------------------------------------------------------
// merged q/k/v projection: grid (8, 64, 3); z selects tensor set
// ---------------------------------------------------------------------------
__global__ void __launch_bounds__(256,2) gemm_proj(
    const float* __restrict__ bq, const float* __restrict__ bk,
    const float* __restrict__ bv)
{
    extern __shared__ __half smh[];
    const unsigned sb = smem_u32(smh);
    const int z = blockIdx.z;
    const float* bias = (z == 0) ? bq : (z == 1) ? bk : bv;
    __half* C = (z == 0) ? g_qh : (z == 1) ? g_kh : g_vh;
    gemm_body(g_in[z], g_w[z], bias, C, sb,
              blockIdx.y << 7, blockIdx.x << 7, (z == 0) ? 2 : 1);
}

// ---------------------------------------------------------------------------
// fused Wo-GEMM + head_reduce fat kernel, INTERLEAVED block mapping
// ---------------------------------------------------------------------------
__global__ void __launch_bounds__(256,2) wo_and_weight(
    const float* __restrict__ bo, float* __restrict__ outO,
    float* __restrict__ outW)
{
    extern __shared__ __half smh[];
    const int gidx = blockIdx.x >> 1;
    if ((blockIdx.x & 1) == 0) {
        const unsigned sb = smem_u32(smh);
        gemm_body(g_ohh, g_w[3], bo, outO, sb,
                  (gidx >> 3) << 7, (gidx & 7) << 7, 0);
        return;
    }

    float* trb = (float*)smh;
    const int lane = threadIdx.x & 31, warp = threadIdx.x >> 5;
    const int b = gidx >> 7, tile_t = gidx & 127;
    const int r = (lane & 7) + (((lane >> 3) & 1) << 3);
    const int cbase = (lane >> 4) << 3;
    const float invH = 1.0f / (float)HEADS;
    float* tr = trb + warp * 16 * 66;

    for (int ts = warp; ts < SEQ/64; ts += 8) {
        float2 acc[4][4];
        #pragma unroll
        for (int k = 0; k < 4; k++)
            #pragma unroll
            for (int j = 0; j < 4; j++) acc[k][j] = make_float2(0.f, 0.f);

        for (int h = 0; h < HEADS; h++) {
            const int bh = b * HEADS + h;
            const size_t tb4 = ((((size_t)bh*(SEQ/16) + tile_t)*(SEQ/64) + ts)*512) >> 2;
            const uint4* p = (const uint4*)g_expa + tb4 + lane;
            const float rl = __ldg(&g_rl[(size_t)bh*SEQ + (tile_t << 4) + r]);
            #pragma unroll
            for (int k = 0; k < 4; k++) {
                uint4 u = __ldg(p + (k << 5));
                float2 f0 = __half22float2(*(__half2*)&u.x);
                float2 f1 = __half22float2(*(__half2*)&u.y);
                float2 f2 = __half22float2(*(__half2*)&u.z);
                float2 f3 = __half22float2(*(__half2*)&u.w);
                acc[k][0].x += f0.x*rl; acc[k][0].y += f0.y*rl;
                acc[k][1].x += f1.x*rl; acc[k][1].y += f1.y*rl;
                acc[k][2].x += f2.x*rl; acc[k][2].y += f2.y*rl;
                acc[k][3].x += f3.x*rl; acc[k][3].y += f3.y*rl;
            }
        }

        #pragma unroll
        for (int k = 0; k < 4; k++)
            #pragma unroll
            for (int j = 0; j < 4; j++) {
                const int c = cbase + (k << 4) + (j << 1);
                tr[r*66 + c]     = acc[k][j].x * invH;
                tr[r*66 + c + 1] = acc[k][j].y * invH;
            }
        __syncwarp();
        #pragma unroll
        for (int rr = 0; rr < 16; rr++) {
            float2 v = *(float2*)&tr[rr*66 + (lane << 1)];
            *(float2*)(outW + ((size_t)b*SEQ + (tile_t<<4) + rr)*SEQ + (ts<<6) + (lane<<1)) = v;
        }
        __syncwarp();
    }
}

// ---------------------------------------------------------------------------
// attn_o: 8 warps x 16 rows, 2 CTAs/SM; 4-stage K/V cp.async pipeline,
// ONE barrier per s-tile (gemm_body pattern). Dynamic smem.
// ---------------------------------------------------------------------------
#define LDK 72
#define A_STB (64*LDK*2)                 // bytes per tensor-stage (9216)
#define A_SMEM_BYTES (8 * A_STB)         // 4 K-stages + 4 V-stages = 73728

__global__ void __launch_bounds__(256,2) attn_o_fp16()
{
    extern __shared__ __half smA[];
    const unsigned sb = smem_u32(smA);

    const int tid  = threadIdx.x;
    const int lane = tid & 31, warp = tid >> 5;
    const int g = lane >> 2, t = lane & 3;
    const int t0 = blockIdx.x << 7;                 // 128 rows per block
    const int bh = blockIdx.y;
    const int b = bh >> 4, h = bh & 15;
    const size_t base = (size_t)b * SEQ * DIM + (size_t)h * HD;
    const __half* qb = g_qh + base;
    const __half* kb = g_kh + base;
    const __half* vb = g_vh + base;
    const int row0 = t0 + (warp << 4) + g;
    const int tile_t = (t0 >> 4) + warp;
    unsigned* ebw = g_expa + ((size_t)bh*(SEQ/16) + tile_t)*(SEQ/64)*512 + lane;

    unsigned qf[4][4];
    #pragma unroll
    for (int ks = 0; ks < 4; ks++) {
        const int c0 = (ks << 4) + (t << 1);
        qf[ks][0] = *(const unsigned*)(qb + (size_t)row0       * DIM + c0);
        qf[ks][1] = *(const unsigned*)(qb + (size_t)(row0 + 8) * DIM + c0);
        qf[ks][2] = *(const unsigned*)(qb + (size_t)row0       * DIM + c0 + 8);
        qf[ks][3] = *(const unsigned*)(qb + (size_t)(row0 + 8) * DIM + c0 + 8);
    }

    float oacc[8][4];
    #pragma unroll
    for (int i = 0; i < 8; i++)
        #pragma unroll
        for (int v = 0; v < 4; v++) oacc[i][v] = 0.f;
    float lp0 = 0.f, lp1 = 0.f;

    const int mi = lane >> 3, mj = lane & 7;
    const int r0c = tid >> 3,         c0c = (tid & 7) << 3;
    const int r1c = (tid + 256) >> 3, c1c = c0c;
    const unsigned kOff0 = (unsigned)((r0c*LDK + c0c) << 1);
    const unsigned kOff1 = (unsigned)((r1c*LDK + c1c) << 1);

    // prologue: tiles 0..2 -> stages 0..2
    #pragma unroll
    for (int s = 0; s < 3; s++) {
        const unsigned kS = sb + (unsigned)(s * A_STB);
        const unsigned vS = kS + (unsigned)(4 * A_STB);
        const size_t gof = (size_t)(s << 6) * DIM;
        cpa16(kS + kOff0, kb + gof + (size_t)r0c * DIM + c0c);
        cpa16(kS + kOff1, kb + gof + (size_t)r1c * DIM + c1c);
        cpa16(vS + kOff0, vb + gof + (size_t)r0c * DIM + c0c);
        cpa16(vS + kOff1, vb + gof + (size_t)r1c * DIM + c1c);
        asm volatile("cp.async.commit_group;\n");
    }

    for (int i = 0; i < SEQ/64; i++) {            // 32 iterations
        if (i <= 29)      asm volatile("cp.async.wait_group 2;\n");
        else if (i == 30) asm volatile("cp.async.wait_group 1;\n");
        else              asm volatile("cp.async.wait_group 0;\n");
        __syncthreads();

        // issue tile i+3 into stage (i+3)&3 == (i-1)&3 (read-complete pre-barrier)
        if (i + 3 < SEQ/64) {
            const int s = (i + 3) & 3;
            const unsigned kS = sb + (unsigned)(s * A_STB);
            const unsigned vS = kS + (unsigned)(4 * A_STB);
            const size_t gof = (size_t)((i + 3) << 6) * DIM;
            cpa16(kS + kOff0, kb + gof + (size_t)r0c * DIM + c0c);
            cpa16(kS + kOff1, kb + gof + (size_t)r1c * DIM + c1c);
            cpa16(vS + kOff0, vb + gof + (size_t)r0c * DIM + c0c);
            cpa16(vS + kOff1, vb + gof + (size_t)r1c * DIM + c1c);
            asm volatile("cp.async.commit_group;\n");
        }

        const __half* ksp = smA + (size_t)((i & 3) * A_STB) / 2;
        const unsigned vsb = sb + (unsigned)(((i & 3) + 4) * A_STB);
        unsigned* eb = ebw + (size_t)i * 512;

        float sc[8][4];
        #pragma unroll
        for (int x = 0; x < 8; x++)
            #pragma unroll
            for (int v = 0; v < 4; v++) sc[x][v] = 0.f;
        #pragma unroll
        for (int ks = 0; ks < 4; ks++) {
            const int kc = (ks << 4) + (t << 1);
            #pragma unroll
            for (int nt = 0; nt < 8; nt++) {
                unsigned b0 = *(const unsigned*)&ksp[((nt<<3)+g)*LDK + kc];
                unsigned b1 = *(const unsigned*)&ksp[((nt<<3)+g)*LDK + kc + 8];
                mma16(sc[nt], qf[ks][0], qf[ks][1], qf[ks][2], qf[ks][3], b0, b1);
            }
        }

        unsigned ph[8][2];
        #pragma unroll
        for (int nt = 0; nt < 8; nt++) {
            float e0 = __expf(fminf(sc[nt][0], 11.f));
            float e1 = __expf(fminf(sc[nt][1], 11.f));
            float e2 = __expf(fminf(sc[nt][2], 11.f));
            float e3 = __expf(fminf(sc[nt][3], 11.f));
            lp0 += e0 + e1;
            lp1 += e2 + e3;
            ph[nt][0] = h2u(__floats2half2_rn(e0, e1));
            ph[nt][1] = h2u(__floats2half2_rn(e2, e3));
            eb[(2*nt    ) << 5] = ph[nt][0];
            eb[(2*nt + 1) << 5] = ph[nt][1];
        }

        #pragma unroll
        for (int ks2 = 0; ks2 < 4; ks2++) {
            const unsigned a0 = ph[2*ks2][0],   a1 = ph[2*ks2][1];
            const unsigned a2 = ph[2*ks2+1][0], a3 = ph[2*ks2+1][1];
            #pragma unroll
            for (int p = 0; p < 4; p++) {
                const int vrow = (ks2 << 4) + ((mi & 1) << 3) + mj;
                const int vcol = (p << 4) + ((mi >> 1) << 3);
                unsigned r[4];
                ldmx4t(r, vsb + (unsigned)((vrow*LDK + vcol) << 1));
                mma16(oacc[2*p],   a0, a1, a2, a3, r[0], r[1]);
                mma16(oacc[2*p+1], a0, a1, a2, a3, r[2], r[3]);
            }
        }
    }

    lp0 += __shfl_xor_sync(0xffffffffu, lp0, 1);
    lp0 += __shfl_xor_sync(0xffffffffu, lp0, 2);
    lp1 += __shfl_xor_sync(0xffffffffu, lp1, 1);
    lp1 += __shfl_xor_sync(0xffffffffu, lp1, 2);
    const float rl0 = 1.0f / lp0;
    const float rl1 = 1.0f / lp1;
    if (t == 0) {
        g_rl[(size_t)bh * SEQ + row0]     = rl0;
        g_rl[(size_t)bh * SEQ + row0 + 8] = rl1;
    }
    #pragma unroll
    for (int nt = 0; nt < 8; nt++) {
        const int c = h*HD + (nt << 3) + (t << 1);
        *(__half2*)(g_ohh + (size_t)(b*SEQ + row0)     * DIM + c) =
            __floats2half2_rn(oacc[nt][0]*rl0, oacc[nt][1]*rl0);
        *(__half2*)(g_ohh + (size_t)(b*SEQ + row0 + 8) * DIM + c) =
            __floats2half2_rn(oacc[nt][2]*rl1, oacc[nt][3]*rl1);
    }
}

// ---------------------------------------------------------------------------
extern "C" void kernel_launch(void* const* d_in, const int* in_sizes, int n_in,
                              void* d_out, int out_size)
{
    const float* Q  = (const float*)d_in[0];
    const float* K  = (const float*)d_in[1];
    const float* V  = (const float*)d_in[2];
    const float* Wq = (const float*)d_in[3];
    const float* bq = (const float*)d_in[4];
    const float* Wk = (const float*)d_in[5];
    const float* bk = (const float*)d_in[6];
    const float* Wv = (const float*)d_in[7];
    const float* bv = (const float*)d_in[8];
    const float* Wo = (const float*)d_in[9];
    const float* bo = (const float*)d_in[10];

    float* outO = (float*)d_out;                       // [B,T,D]
    float* outW = outO + (size_t)BATCH * SEQ * DIM;    // [B,T,T]

    cudaFuncSetAttribute(gemm_proj,     cudaFuncAttributeMaxDynamicSharedMemorySize, G_SMEM_BYTES);
    cudaFuncSetAttribute(wo_and_weight, cudaFuncAttributeMaxDynamicSharedMemorySize, G_SMEM_BYTES);
    cudaFuncSetAttribute(attn_o_fp16,   cudaFuncAttributeMaxDynamicSharedMemorySize, A_SMEM_BYTES);

    cvt_all<<<dim3(1024, 7), 256>>>(Q, K, V, Wq, Wk, Wv, Wo);

    gemm_proj<<<dim3(DIM/128, MTOT/128, 3), 256, G_SMEM_BYTES>>>(bq, bk, bv);

    attn_o_fp16<<<dim3(SEQ/128, BATCH*HEADS), 256, A_SMEM_BYTES>>>();

    wo_and_weight<<<1024, 256, G_SMEM_BYTES>>>(bo, outO, outW);
}